// round 16
// baseline (speedup 1.0000x reference)
#include <cuda_runtime.h>
#include <cstdint>

#define N_USERS 50000
#define N_ITEMS 100000
#define N_NODES 150000
#define NNZ     1000000
#define D       64
#define ND      (N_NODES * D)      /* 9,600,000 */
#define NW      (ND / 16)          /* 600,000 mask words (u16) per hop */
#define N_HOPS  3

// keep message iff bits < 0xE6666600  (== u01(bits) < 0.9f exactly)
#define MSG_TH  0xE6666600u

#define NB_INIT 9375               /* ND/4/256 exact */
#define NB_EDGE 977                /* ceil(NNZ/4 / 256): 4 edges/thread */
#define NB_MASK 2344               /* ceil(NW / 256): 16 ciphers -> 1 u16/thread */
#define NB_A    (NB_INIT + NB_EDGE + NB_MASK)   /* 12696 */
#define EPG     4                  /* edges per 16-thread group in spmm */
#define CAP_EDGES 516096           /* kept-edge cap (expected 500k, +32 sigma) */
#define NB_SPMM ((CAP_EDGES / EPG) * 16 / 256)  /* 8064 */
#define NB_B    (NB_SPMM + NB_MASK)             /* 10408 */

// Scratch (no cudaMalloc allowed)
__device__ int4     g_edges[N_HOPS][NNZ]; // compacted kept edges {row,col,valbits,0}
__device__ uint16_t g_maskb[N_HOPS][NW];  // bit-packed keep mask (1 bit/element)
__device__ int      g_cnt[4];             // kept-edge counters (0 at module load;
                                          // k_tail re-zeroes -> replay-safe)

// ---------------------------------------------------------------------------
// JAX threefry2x32.  Host version (key derivation) + device version with adds
// on the fma pipe (IMAD via runtime-opaque multiplier `one`).
// ---------------------------------------------------------------------------
__host__ __forceinline__ uint32_t rotl32h(uint32_t x, int r) {
    return (x << r) | (x >> (32 - r));
}

__host__ void threefry2x32_host(uint32_t k0, uint32_t k1, uint32_t x0, uint32_t x1,
                                uint32_t& o0, uint32_t& o1)
{
    uint32_t ks2 = k0 ^ k1 ^ 0x1BD11BDAu;
    x0 += k0; x1 += k1;
#define TF_R4(a,b,c,d)                                   \
    x0 += x1; x1 = rotl32h(x1,(a)); x1 ^= x0;            \
    x0 += x1; x1 = rotl32h(x1,(b)); x1 ^= x0;            \
    x0 += x1; x1 = rotl32h(x1,(c)); x1 ^= x0;            \
    x0 += x1; x1 = rotl32h(x1,(d)); x1 ^= x0;
    TF_R4(13,15,26,6);   x0 += k1;  x1 += ks2 + 1u;
    TF_R4(17,29,16,24);  x0 += ks2; x1 += k0  + 2u;
    TF_R4(13,15,26,6);   x0 += k0;  x1 += k1  + 3u;
    TF_R4(17,29,16,24);  x0 += k1;  x1 += ks2 + 4u;
    TF_R4(13,15,26,6);   x0 += ks2; x1 += k0  + 5u;
#undef TF_R4
    o0 = x0; o1 = x1;
}

__device__ __forceinline__ uint32_t addi(uint32_t a, uint32_t b, uint32_t one) {
    uint32_t d;
    asm("mad.lo.u32 %0, %1, %2, %3;" : "=r"(d) : "r"(a), "r"(one), "r"(b));
    return d;
}

__device__ __forceinline__ uint32_t rotxor(uint32_t x, int r, uint32_t y) {
    return __funnelshift_l(x, x, (unsigned)r) ^ y;
}

__device__ __forceinline__ void tf_round4(uint32_t& x0, uint32_t& x1,
                                          int a, int b, int c, int d,
                                          uint32_t one)
{
    x0 = addi(x0, x1, one); x1 = rotxor(x1, a, x0);
    x0 = addi(x0, x1, one); x1 = rotxor(x1, b, x0);
    x0 = addi(x0, x1, one); x1 = rotxor(x1, c, x0);
    x0 = addi(x0, x1, one); x1 = rotxor(x1, d, x0);
}

// Partitionable-mode random bits at flat index i: block (0, i), bits = o0^o1.
__device__ __forceinline__ uint32_t tf_bits_i(uint32_t k0, uint32_t k1,
                                              uint32_t ks2, uint32_t i,
                                              uint32_t one)
{
    uint32_t x0 = k0;                 // 0 + k0
    uint32_t x1 = addi(i, k1, one);
    tf_round4(x0, x1, 13, 15, 26,  6, one);
    x0 = addi(x0, k1,  one); x1 = addi(x1, ks2 + 1u, one);
    tf_round4(x0, x1, 17, 29, 16, 24, one);
    x0 = addi(x0, ks2, one); x1 = addi(x1, k0  + 2u, one);
    tf_round4(x0, x1, 13, 15, 26,  6, one);
    x0 = addi(x0, k0,  one); x1 = addi(x1, k1  + 3u, one);
    tf_round4(x0, x1, 17, 29, 16, 24, one);
    x0 = addi(x0, k1,  one); x1 = addi(x1, ks2 + 4u, one);
    tf_round4(x0, x1, 13, 15, 26,  6, one);
    x0 = addi(x0, ks2, one); x1 = addi(x1, k0  + 5u, one);
    return x0 ^ x1;
}

// ---------------------------------------------------------------------------
// Maskgen block body: thread t covers elements [t*16, t*16+16): 16 ciphers ->
// one bit-packed u16.  Optionally zeroes 4 float4s of the out slice at
// zero_off (deferred zeroing for a later spmm's destination).
// ---------------------------------------------------------------------------
__device__ __forceinline__ void maskgen_body(int t, uint16_t* __restrict__ mp,
                                             float4* __restrict__ out,
                                             unsigned zero_off,
                                             uint32_t k0, uint32_t k1,
                                             uint32_t one)
{
    if (t >= NW) return;
    uint32_t ks2 = k0 ^ k1 ^ 0x1BD11BDAu;
    uint32_t j = (uint32_t)t * 16u;

    uint32_t pack = 0u;
#pragma unroll
    for (int i = 0; i < 16; i++) {
        uint32_t b = tf_bits_i(k0, k1, ks2, j + (uint32_t)i, one);
        pack |= (b < MSG_TH ? 1u : 0u) << i;
    }
    mp[t] = (uint16_t)pack;

    if (zero_off) {
        // 16 elements = 4 float4s; j%64 in {0,16,32,48} -> never straddles a row
        unsigned n = j >> 6;
        unsigned z = n * 64u + zero_off + ((j & 63u) >> 2);
        float4 zv = make_float4(0.f, 0.f, 0.f, 0.f);
        out[z]     = zv;
        out[z + 1] = zv;
        out[z + 2] = zv;
        out[z + 3] = zv;
    }
}

// ---------------------------------------------------------------------------
// Kernel A: three block roles interleaved by a Bresenham split so memory-
// bound init blocks co-reside with ALU-bound edge/mask blocks:
//   mem  (NB_INIT): out slice0 = embeddings
//   alu  (NB_EDGE): edge dropout + compaction for all 3 hops, 4 edges/thread
//   alu  (NB_MASK): bit-packed message mask for hop 0 + zero slice1
// ---------------------------------------------------------------------------
__global__ void k_A(const float4* __restrict__ ue, const float4* __restrict__ ie,
                    float4* __restrict__ out,
                    const float4* __restrict__ vals,
                    const int4*  __restrict__ rows,
                    const int4*  __restrict__ cols,
                    uint32_t ke00, uint32_t ke01,
                    uint32_t ke10, uint32_t ke11,
                    uint32_t ke20, uint32_t ke21,
                    uint32_t km00, uint32_t km01,
                    uint32_t one)
{
    unsigned bid = blockIdx.x;
    unsigned long long pp = (unsigned long long)bid * NB_INIT;
    unsigned before = (unsigned)(pp / NB_A);
    unsigned after  = (unsigned)((pp + NB_INIT) / NB_A);

    if (after > before) {
        // ---- mem role: init (slice0 only; slice1 zeroed by mask role) ----
        int i = (int)before * 256 + threadIdx.x;   // over ND/4, exact
        int node = i >> 4;
        int q    = i & 15;
        float4 v = (node < N_USERS) ? ue[node * 16 + q]
                                    : ie[(node - N_USERS) * 16 + q];
        out[(unsigned)node * 64u + (unsigned)q] = v;
        return;
    }

    unsigned aid = bid - before;          // [0, NB_EDGE + NB_MASK)
    if (aid >= NB_EDGE) {
        // ---- alu role: mask for hop 0 + zero slice1 ----
        int t = (int)(aid - NB_EDGE) * 256 + threadIdx.x;
        maskgen_body(t, g_maskb[0], out, 16u, km00, km01, one);
        return;
    }

    // ---- alu role: edge dropout + compaction, 4 edges/thread, 3 hops ----
    int t    = (int)aid * 256 + threadIdx.x;
    int lane = threadIdx.x & 31;
    bool live = (t < NNZ / 4);

    float4 v  = make_float4(0.f, 0.f, 0.f, 0.f);
    int4   rr = make_int4(0, 0, 0, 0), cc = make_int4(0, 0, 0, 0);
    if (live) { v = vals[t]; rr = rows[t]; cc = cols[t]; }
    float vv[4] = {v.x, v.y, v.z, v.w};
    int   ra[4] = {rr.x, rr.y, rr.z, rr.w};
    int   ca[4] = {cc.x, cc.y, cc.z, cc.w};
    uint32_t j  = (uint32_t)t * 4u;

    uint32_t K0[3] = {ke00, ke10, ke20};
    uint32_t K1[3] = {ke01, ke11, ke21};

#pragma unroll
    for (int h = 0; h < N_HOPS; h++) {
        uint32_t ks2 = K0[h] ^ K1[h] ^ 0x1BD11BDAu;
        int4 e[4];
        int kept = 0;
        if (live) {
#pragma unroll
            for (int i = 0; i < 4; i++) {
                uint32_t b = tf_bits_i(K0[h], K1[h], ks2, j + (uint32_t)i, one);
                if ((int)b < 0) {                     // keep: u >= 0.5
                    e[kept] = make_int4(ra[i], ca[i],
                                        __float_as_int(vv[i] * 2.0f), 0);
                    kept++;
                }
            }
        }
        int off = kept;
#pragma unroll
        for (int d = 1; d < 32; d <<= 1) {
            int nn = __shfl_up_sync(0xFFFFFFFFu, off, d);
            if (lane >= d) off += nn;
        }
        int total = __shfl_sync(0xFFFFFFFFu, off, 31);
        int base  = 0;
        if (lane == 31 && total > 0) base = atomicAdd(&g_cnt[h], total);
        base = __shfl_sync(0xFFFFFFFFu, base, 31);

        int pos = base + off - kept;
#pragma unroll
        for (int i = 0; i < 4; i++)
            if (i < kept) g_edges[h][pos + i] = e[i];
    }
}

// ---------------------------------------------------------------------------
// Kernel B (per hop): spmm blocks (scatter with INLINE bit-packed message-
// dropout mask) interleaved with maskgen blocks for the NEXT hop (and
// deferred zeroing of the next hop's destination slice).
// nb_total == NB_SPMM -> spmm only.
// ---------------------------------------------------------------------------
__global__ void __launch_bounds__(256, 5)
k_B(float4* __restrict__ out,
    const float4* __restrict__ ue, const float4* __restrict__ ie,
    int hop, unsigned src_off, unsigned dst_off,
    unsigned nb_total, unsigned zero_off,
    uint32_t mk0, uint32_t mk1, uint32_t one)
{
    unsigned bid = blockIdx.x;
    unsigned long long pp = (unsigned long long)bid * NB_SPMM;
    unsigned before = (unsigned)(pp / nb_total);
    unsigned after  = (unsigned)((pp + NB_SPMM) / nb_total);

    if (after == before) {
        // ---- maskgen role for hop+1 (+ zero slice hop+2) ----
        int t = (int)(bid - before) * 256 + threadIdx.x;
        maskgen_body(t, g_maskb[hop + 1], out, zero_off, mk0, mk1, one);
        return;
    }

    // ---- spmm role ----
    unsigned g  = before * 256u + threadIdx.x;
    int      eg = (int)(g >> 4);
    unsigned t  = g & 15u;
    int count = g_cnt[hop];
    int base  = eg * EPG;
    if (base >= count) return;
    int n = count - base; if (n > EPG) n = EPG;

    const int4* E = g_edges[hop];
    const uint16_t* M = g_maskb[hop];
    int4 m[EPG];
#pragma unroll
    for (int i = 0; i < EPG; i++)
        if (i < n) m[i] = E[base + i];

    float4 a[EPG];
    uint32_t w[EPG];
    unsigned hw_idx = t >> 2;          // which u16 of the row's 4
    unsigned hw_sh  = (t & 3u) * 4u;   // bit offset of this thread's 4 bits
#pragma unroll
    for (int i = 0; i < EPG; i++) {
        if (i < n) {
            unsigned c = (unsigned)m[i].y;
            const float4* p;
            if (hop == 0)
                p = (c < N_USERS) ? (ue + c * 16u)
                                  : (ie + (c - N_USERS) * 16u);
            else
                p = out + (c * 64u + src_off);
            a[i] = p[t];
            w[i] = (uint32_t)M[(unsigned)m[i].x * 4u + hw_idx] >> hw_sh;
        }
    }

    const float s = 1.0f / 0.9f;
#pragma unroll
    for (int i = 0; i < EPG; i++) {
        if (i < n) {
            float vs = __int_as_float(m[i].z) * s;
            float f0 = (w[i] & 1u) ? vs : 0.0f;
            float f1 = (w[i] & 2u) ? vs : 0.0f;
            float f2 = (w[i] & 4u) ? vs : 0.0f;
            float f3 = (w[i] & 8u) ? vs : 0.0f;
            float4* d = out + ((unsigned)m[i].x * 64u + dst_off + t);
            asm volatile("red.global.add.v4.f32 [%0], {%1, %2, %3, %4};"
                         :: "l"(d), "f"(a[i].x * f0), "f"(a[i].y * f1),
                            "f"(a[i].z * f2), "f"(a[i].w * f3)
                         : "memory");
        }
    }
}

// Tail: clear counters for the next graph replay.
__global__ void k_tail()
{
    if (threadIdx.x < 4) g_cnt[threadIdx.x] = 0;
}

// ---------------------------------------------------------------------------
// Launch
// ---------------------------------------------------------------------------
extern "C" void kernel_launch(void* const* d_in, const int* in_sizes, int n_in,
                              void* d_out, int out_size)
{
    const float4* ue   = (const float4*)d_in[0];
    const float4* ie   = (const float4*)d_in[1];
    const int4*   rows = (const int4*)d_in[2];
    const int4*   cols = (const int4*)d_in[3];
    const float4* vals = (const float4*)d_in[4];
    float4*       out  = (float4*)d_out;

    // Partitionable ("fold-like") split: split(key,3)[i] = threefry(key, (0,i))
    uint32_t key0 = 0u, key1 = 42u;   // jax.random.key(42)
    uint32_t ke[N_HOPS][2], km[N_HOPS][2];
    for (int h = 0; h < N_HOPS; h++) {
        uint32_t n0, n1;
        threefry2x32_host(key0, key1, 0u, 0u, n0, n1);
        threefry2x32_host(key0, key1, 0u, 1u, ke[h][0], ke[h][1]);
        threefry2x32_host(key0, key1, 0u, 2u, km[h][0], km[h][1]);
        key0 = n0; key1 = n1;
    }

    const int B = 256;
    const uint32_t one = 1u;   // runtime-opaque multiplier for IMAD adds

    k_A<<<NB_A, B>>>(ue, ie, out, vals, rows, cols,
                     ke[0][0], ke[0][1], ke[1][0], ke[1][1], ke[2][0], ke[2][1],
                     km[0][0], km[0][1], one);

    // B0: spmm hop0 + maskgen hop1 + zero slice2
    k_B<<<NB_B, B>>>(out, ue, ie, 0, 0u, 16u, NB_B, 32u,
                     km[1][0], km[1][1], one);
    // B1: spmm hop1 + maskgen hop2 + zero slice3
    k_B<<<NB_B, B>>>(out, ue, ie, 1, 16u, 32u, NB_B, 48u,
                     km[2][0], km[2][1], one);
    // B2: spmm hop2 only
    k_B<<<NB_SPMM, B>>>(out, ue, ie, 2, 32u, 48u, NB_SPMM, 0u,
                        0u, 0u, one);

    k_tail<<<1, 32>>>();
}

// round 17
// speedup vs baseline: 1.1045x; 1.1045x over previous
#include <cuda_runtime.h>
#include <cstdint>

#define N_USERS 50000
#define N_ITEMS 100000
#define N_NODES 150000
#define NNZ     1000000
#define D       64
#define ND      (N_NODES * D)      /* 9,600,000 */
#define N_HOPS  3

// keep message iff bits < 0xE6666600  (== u01(bits) < 0.9f exactly)
#define MSG_TH  0xE6666600u

#define NB_INIT 9375               /* ND/4/256 exact */
#define NB_EDGE 977                /* ceil(NNZ/4 / 256): 4 edges/thread */
#define NB_MASK 4688               /* ceil(ND/8 / 256): 8 ciphers/thread */
#define NB_A    (NB_EDGE + NB_MASK)             /* 5665: pure-ALU kernel A */
#define EPG     4                  /* edges per 16-thread group in spmm */
#define CAP_EDGES 516096           /* kept-edge cap (expected 500k, +32 sigma) */
#define NB_SPMM ((CAP_EDGES / EPG) * 16 / 256)  /* 8064 */
#define NB_B01  (NB_SPMM + NB_MASK)             /* 12752 */
#define NB_B2   (NB_SPMM + NB_INIT)             /* 17439 */

// Scratch (no cudaMalloc allowed)
__device__ int4    g_edges[N_HOPS][NNZ]; // compacted kept edges {row,col,valbits,0}
__device__ uint8_t g_mask[N_HOPS][ND];   // per-element keep mask (1 byte each)
__device__ int     g_cnt[3];             // kept-edge counters (0 at module load;
                                         // B2 block 0 re-zeroes -> replay-safe)
__device__ int     g_cnt2;               // snapshot of g_cnt[2] (B1 -> B2)

// ---------------------------------------------------------------------------
// JAX threefry2x32.  Host version (key derivation) + device version with adds
// on the fma pipe (IMAD via runtime-opaque multiplier `one`).
// ---------------------------------------------------------------------------
__host__ __forceinline__ uint32_t rotl32h(uint32_t x, int r) {
    return (x << r) | (x >> (32 - r));
}

__host__ void threefry2x32_host(uint32_t k0, uint32_t k1, uint32_t x0, uint32_t x1,
                                uint32_t& o0, uint32_t& o1)
{
    uint32_t ks2 = k0 ^ k1 ^ 0x1BD11BDAu;
    x0 += k0; x1 += k1;
#define TF_R4(a,b,c,d)                                   \
    x0 += x1; x1 = rotl32h(x1,(a)); x1 ^= x0;            \
    x0 += x1; x1 = rotl32h(x1,(b)); x1 ^= x0;            \
    x0 += x1; x1 = rotl32h(x1,(c)); x1 ^= x0;            \
    x0 += x1; x1 = rotl32h(x1,(d)); x1 ^= x0;
    TF_R4(13,15,26,6);   x0 += k1;  x1 += ks2 + 1u;
    TF_R4(17,29,16,24);  x0 += ks2; x1 += k0  + 2u;
    TF_R4(13,15,26,6);   x0 += k0;  x1 += k1  + 3u;
    TF_R4(17,29,16,24);  x0 += k1;  x1 += ks2 + 4u;
    TF_R4(13,15,26,6);   x0 += ks2; x1 += k0  + 5u;
#undef TF_R4
    o0 = x0; o1 = x1;
}

__device__ __forceinline__ uint32_t addi(uint32_t a, uint32_t b, uint32_t one) {
    uint32_t d;
    asm("mad.lo.u32 %0, %1, %2, %3;" : "=r"(d) : "r"(a), "r"(one), "r"(b));
    return d;
}

__device__ __forceinline__ uint32_t rotxor(uint32_t x, int r, uint32_t y) {
    return __funnelshift_l(x, x, (unsigned)r) ^ y;
}

__device__ __forceinline__ void tf_round4(uint32_t& x0, uint32_t& x1,
                                          int a, int b, int c, int d,
                                          uint32_t one)
{
    x0 = addi(x0, x1, one); x1 = rotxor(x1, a, x0);
    x0 = addi(x0, x1, one); x1 = rotxor(x1, b, x0);
    x0 = addi(x0, x1, one); x1 = rotxor(x1, c, x0);
    x0 = addi(x0, x1, one); x1 = rotxor(x1, d, x0);
}

// Partitionable-mode random bits at flat index i: block (0, i), bits = o0^o1.
__device__ __forceinline__ uint32_t tf_bits_i(uint32_t k0, uint32_t k1,
                                              uint32_t ks2, uint32_t i,
                                              uint32_t one)
{
    uint32_t x0 = k0;                 // 0 + k0
    uint32_t x1 = addi(i, k1, one);
    tf_round4(x0, x1, 13, 15, 26,  6, one);
    x0 = addi(x0, k1,  one); x1 = addi(x1, ks2 + 1u, one);
    tf_round4(x0, x1, 17, 29, 16, 24, one);
    x0 = addi(x0, ks2, one); x1 = addi(x1, k0  + 2u, one);
    tf_round4(x0, x1, 13, 15, 26,  6, one);
    x0 = addi(x0, k0,  one); x1 = addi(x1, k1  + 3u, one);
    tf_round4(x0, x1, 17, 29, 16, 24, one);
    x0 = addi(x0, k1,  one); x1 = addi(x1, ks2 + 4u, one);
    tf_round4(x0, x1, 13, 15, 26,  6, one);
    x0 = addi(x0, ks2, one); x1 = addi(x1, k0  + 5u, one);
    return x0 ^ x1;
}

// ---------------------------------------------------------------------------
// Maskgen block body: thread t covers elements [t*8, t*8+8): 8 ciphers ->
// 8 mask bytes packed in one 64-bit store.  Optionally zeroes the out slice
// at zero_off (deferred zeroing for a later spmm's destination).
// ---------------------------------------------------------------------------
__device__ __forceinline__ void maskgen_body(int t, uint8_t* __restrict__ mp,
                                             float4* __restrict__ out,
                                             unsigned zero_off,
                                             uint32_t k0, uint32_t k1,
                                             uint32_t one)
{
    if (t >= ND / 8) return;
    uint32_t ks2 = k0 ^ k1 ^ 0x1BD11BDAu;
    uint32_t j = (uint32_t)t * 8u;

    unsigned long long pack = 0ull;
#pragma unroll
    for (int i = 0; i < 8; i++) {
        uint32_t b = tf_bits_i(k0, k1, ks2, j + (uint32_t)i, one);
        pack |= (unsigned long long)(b < MSG_TH ? 1u : 0u) << (i * 8);
    }
    *(unsigned long long*)(mp + j) = pack;

    if (zero_off) {
        unsigned n = j >> 6;
        unsigned z = n * 64u + zero_off + ((j & 63u) >> 2);
        float4 zv = make_float4(0.f, 0.f, 0.f, 0.f);
        out[z]     = zv;
        out[z + 1] = zv;
    }
}

// ---------------------------------------------------------------------------
// Kernel A (pure ALU): edge dropout + compaction for all 3 hops (977 blocks,
// 4 edges/thread) and hop-0 message mask + slice1 zeroing (4688 blocks).
// Slice-0 init has moved to kernel B2 (it is pure output, nothing reads it).
// ---------------------------------------------------------------------------
__global__ void k_A(float4* __restrict__ out,
                    const float4* __restrict__ vals,
                    const int4*  __restrict__ rows,
                    const int4*  __restrict__ cols,
                    uint32_t ke00, uint32_t ke01,
                    uint32_t ke10, uint32_t ke11,
                    uint32_t ke20, uint32_t ke21,
                    uint32_t km00, uint32_t km01,
                    uint32_t one)
{
    unsigned bid = blockIdx.x;
    if (bid >= NB_EDGE) {
        // ---- mask for hop 0 + zero slice1 ----
        int t = (int)(bid - NB_EDGE) * 256 + threadIdx.x;
        maskgen_body(t, g_mask[0], out, 16u, km00, km01, one);
        return;
    }

    // ---- edge dropout + compaction, 4 edges/thread, 3 hops ----
    int t    = (int)bid * 256 + threadIdx.x;
    int lane = threadIdx.x & 31;
    bool live = (t < NNZ / 4);

    float4 v  = make_float4(0.f, 0.f, 0.f, 0.f);
    int4   rr = make_int4(0, 0, 0, 0), cc = make_int4(0, 0, 0, 0);
    if (live) { v = vals[t]; rr = rows[t]; cc = cols[t]; }
    float vv[4] = {v.x, v.y, v.z, v.w};
    int   ra[4] = {rr.x, rr.y, rr.z, rr.w};
    int   ca[4] = {cc.x, cc.y, cc.z, cc.w};
    uint32_t j  = (uint32_t)t * 4u;

    uint32_t K0[3] = {ke00, ke10, ke20};
    uint32_t K1[3] = {ke01, ke11, ke21};

#pragma unroll
    for (int h = 0; h < N_HOPS; h++) {
        uint32_t ks2 = K0[h] ^ K1[h] ^ 0x1BD11BDAu;
        int4 e[4];
        int kept = 0;
        if (live) {
#pragma unroll
            for (int i = 0; i < 4; i++) {
                uint32_t b = tf_bits_i(K0[h], K1[h], ks2, j + (uint32_t)i, one);
                if ((int)b < 0) {                     // keep: u >= 0.5
                    e[kept] = make_int4(ra[i], ca[i],
                                        __float_as_int(vv[i] * 2.0f), 0);
                    kept++;
                }
            }
        }
        int off = kept;
#pragma unroll
        for (int d = 1; d < 32; d <<= 1) {
            int nn = __shfl_up_sync(0xFFFFFFFFu, off, d);
            if (lane >= d) off += nn;
        }
        int total = __shfl_sync(0xFFFFFFFFu, off, 31);
        int base  = 0;
        if (lane == 31 && total > 0) base = atomicAdd(&g_cnt[h], total);
        base = __shfl_sync(0xFFFFFFFFu, base, 31);

        int pos = base + off - kept;
#pragma unroll
        for (int i = 0; i < 4; i++)
            if (i < kept) g_edges[h][pos + i] = e[i];
    }
}

// ---------------------------------------------------------------------------
// Kernel B (per hop): spmm blocks (scatter with INLINE message-dropout mask)
// interleaved with helper blocks:
//   rest_role 0 (B0/B1): maskgen for hop+1 + deferred zero of slice hop+2
//   rest_role 1 (B2):    slice-0 init (out[:,0,:] = embeddings)
// copy_cnt (B1): block 0 snapshots g_cnt[2] -> g_cnt2 for B2.
// clear_cnt (B2): block 0 zeroes g_cnt (B2 reads only g_cnt2) -> replay-safe.
// ---------------------------------------------------------------------------
__global__ void __launch_bounds__(256, 5)
k_B(float4* __restrict__ out,
    const float4* __restrict__ ue, const float4* __restrict__ ie,
    int hop, unsigned src_off, unsigned dst_off,
    unsigned nb_total, unsigned zero_off,
    int rest_role, int copy_cnt, int clear_cnt,
    uint32_t mk0, uint32_t mk1, uint32_t one)
{
    unsigned bid = blockIdx.x;
    if (bid == 0 && threadIdx.x == 0) {
        if (copy_cnt)  g_cnt2 = g_cnt[2];
        if (clear_cnt) { g_cnt[0] = 0; g_cnt[1] = 0; g_cnt[2] = 0; }
    }

    unsigned long long pp = (unsigned long long)bid * NB_SPMM;
    unsigned before = (unsigned)(pp / nb_total);
    unsigned after  = (unsigned)((pp + NB_SPMM) / nb_total);

    if (after == before) {
        unsigned r = bid - before;
        if (rest_role) {
            // ---- slice-0 init role (B2): over ND/4, exact ----
            int i = (int)r * 256 + threadIdx.x;
            int node = i >> 4;
            int q    = i & 15;
            float4 v = (node < N_USERS) ? ue[node * 16 + q]
                                        : ie[(node - N_USERS) * 16 + q];
            out[(unsigned)node * 64u + (unsigned)q] = v;
        } else {
            // ---- maskgen role for hop+1 (+ zero slice hop+2) ----
            int t = (int)r * 256 + threadIdx.x;
            maskgen_body(t, g_mask[hop + 1], out, zero_off, mk0, mk1, one);
        }
        return;
    }

    // ---- spmm role ----
    unsigned g  = before * 256u + threadIdx.x;
    int      eg = (int)(g >> 4);
    unsigned t  = g & 15u;
    int count = (hop == 2) ? g_cnt2 : g_cnt[hop];
    int base  = eg * EPG;
    if (base >= count) return;
    int n = count - base; if (n > EPG) n = EPG;

    const int4* E = g_edges[hop];
    const uint8_t* M = g_mask[hop];
    int4 m[EPG];
#pragma unroll
    for (int i = 0; i < EPG; i++)
        if (i < n) m[i] = E[base + i];

    float4 a[EPG];
    uint32_t w[EPG];
#pragma unroll
    for (int i = 0; i < EPG; i++) {
        if (i < n) {
            unsigned c = (unsigned)m[i].y;
            const float4* p;
            if (hop == 0)
                p = (c < N_USERS) ? (ue + c * 16u)
                                  : (ie + (c - N_USERS) * 16u);
            else
                p = out + (c * 64u + src_off);
            a[i] = p[t];
            w[i] = *(const uint32_t*)(M + (unsigned)m[i].x * 64u + t * 4u);
        }
    }

    const float s = 1.0f / 0.9f;
#pragma unroll
    for (int i = 0; i < EPG; i++) {
        if (i < n) {
            float vs = __int_as_float(m[i].z) * s;
            float f0 = (w[i] & 0x000000FFu) ? vs : 0.0f;
            float f1 = (w[i] & 0x0000FF00u) ? vs : 0.0f;
            float f2 = (w[i] & 0x00FF0000u) ? vs : 0.0f;
            float f3 = (w[i] & 0xFF000000u) ? vs : 0.0f;
            float4* d = out + ((unsigned)m[i].x * 64u + dst_off + t);
            asm volatile("red.global.add.v4.f32 [%0], {%1, %2, %3, %4};"
                         :: "l"(d), "f"(a[i].x * f0), "f"(a[i].y * f1),
                            "f"(a[i].z * f2), "f"(a[i].w * f3)
                         : "memory");
        }
    }
}

// ---------------------------------------------------------------------------
// Launch
// ---------------------------------------------------------------------------
extern "C" void kernel_launch(void* const* d_in, const int* in_sizes, int n_in,
                              void* d_out, int out_size)
{
    const float4* ue   = (const float4*)d_in[0];
    const float4* ie   = (const float4*)d_in[1];
    const int4*   rows = (const int4*)d_in[2];
    const int4*   cols = (const int4*)d_in[3];
    const float4* vals = (const float4*)d_in[4];
    float4*       out  = (float4*)d_out;

    // Partitionable ("fold-like") split: split(key,3)[i] = threefry(key, (0,i))
    uint32_t key0 = 0u, key1 = 42u;   // jax.random.key(42)
    uint32_t ke[N_HOPS][2], km[N_HOPS][2];
    for (int h = 0; h < N_HOPS; h++) {
        uint32_t n0, n1;
        threefry2x32_host(key0, key1, 0u, 0u, n0, n1);
        threefry2x32_host(key0, key1, 0u, 1u, ke[h][0], ke[h][1]);
        threefry2x32_host(key0, key1, 0u, 2u, km[h][0], km[h][1]);
        key0 = n0; key1 = n1;
    }

    const int B = 256;
    const uint32_t one = 1u;   // runtime-opaque multiplier for IMAD adds

    // A: edge compaction (all hops) + mask0 + zero slice1 (pure ALU + light mem)
    k_A<<<NB_A, B>>>(out, vals, rows, cols,
                     ke[0][0], ke[0][1], ke[1][0], ke[1][1], ke[2][0], ke[2][1],
                     km[0][0], km[0][1], one);

    // B0: spmm hop0 + maskgen hop1 + zero slice2
    k_B<<<NB_B01, B>>>(out, ue, ie, 0, 0u, 16u, NB_B01, 32u,
                       0, 0, 0, km[1][0], km[1][1], one);
    // B1: spmm hop1 + maskgen hop2 + zero slice3; snapshot g_cnt[2] -> g_cnt2
    k_B<<<NB_B01, B>>>(out, ue, ie, 1, 16u, 32u, NB_B01, 48u,
                       0, 1, 0, km[2][0], km[2][1], one);
    // B2: spmm hop2 (count from g_cnt2) + slice-0 init; clears g_cnt
    k_B<<<NB_B2, B>>>(out, ue, ie, 2, 32u, 48u, NB_B2, 0u,
                      1, 0, 1, 0u, 0u, one);
}